// round 15
// baseline (speedup 1.0000x reference)
#include <cuda_runtime.h>

#define NXC 512
#define NYC 512
#define PHW 3
#define PP 6                   // patch size
#define BB 128
#define SS 1024
#define BH 32                  // band height (rows)
#define BANDS_PER_IMG (NXC / BH)      // 16
#define NBANDS (BB * BANDS_PER_IMG)   // 2048
#define NT 512                 // threads per block
#define CAP 192                // max sources per band (mean ~75)
#define NBKT 16                // 32-col stripes
#define BCAP 32                // per-bucket capacity (mean ~5.5)

__device__ __forceinline__ float inv_alpha() { return 1.0f / (1.41421356237309515f * 0.92f); }

// statically-indexed 6-row accumulate; RL = warp-uniform local patch-origin row
template<int RL>
__device__ __forceinline__ void acc6(float* acc, const float* s_lx, int sb, float ly) {
#pragma unroll
    for (int i = 0; i < PP; ++i) {
        const int r = RL + i;                 // compile-time
        if (r >= 0 && r < BH)
            acc[r] += s_lx[sb + i] * ly;      // static register index
    }
}

__global__ __launch_bounds__(NT, 2) void render_kernel(const float* __restrict__ z,
                                                       float* __restrict__ out) {
    __shared__ float2 s_src[CAP];
    __shared__ float  s_lx[CAP * PP];
    __shared__ float  s_ly[CAP * PP];
    __shared__ int    s_px[CAP];
    __shared__ int    s_py[CAP];
    __shared__ int    s_bcnt[NBKT];
    __shared__ int    s_blist[NBKT][BCAP];    // packed: sid<<16 | (rl+5)<<9 | py
    __shared__ int    s_n;

    int blk = blockIdx.x;
    int b   = blk >> 4;                               // image
    int r0  = (blk & (BANDS_PER_IMG - 1)) << 5;       // first global row of band
    int tid = threadIdx.x;
    int wid = tid >> 5;
    int lane = tid & 31;

    if (tid == 0) s_n = 0;
    if (tid < NBKT) s_bcnt[tid] = 0;
    __syncthreads();

    // 1) scan this image's sources (coalesced), keep those intersecting the band
    {
        const float* zx = z + (size_t)b * 2 * SS;
#pragma unroll
        for (int k = 0; k < SS / NT; ++k) {
            int s = tid + k * NT;
            float x0 = __ldg(&zx[s]);
            float y0 = __ldg(&zx[SS + s]);
            int patchx = __float2int_rn(x0) - PHW;
            int patchy = __float2int_rn(y0) - PHW;
            bool valid = (patchx >= 0) & (patchx < NXC - PP) &
                         (patchy >= 0) & (patchy < NYC - PP);
            bool hit = valid & (patchx >= r0 - (PP - 1)) & (patchx < r0 + BH);
            if (hit) {
                int pos = atomicAdd(&s_n, 1);
                if (pos < CAP) s_src[pos] = make_float2(x0, y0);
            }
        }
    }
    __syncthreads();

    int n = s_n;
    if (n > CAP) n = CAP;

    // 2) per-source-per-axis setup: 2 threads per source
    if (tid < 2 * n) {
        int sid = tid >> 1;
        int ax  = tid & 1;
        float2 xy = s_src[sid];
        float u0 = ax ? xy.y : xy.x;
        int pu = __float2int_rn(u0) - PHW;
        float up = u0 - (float)pu;
        const float ia = inv_alpha();

        float e[PP + 1];
#pragma unroll
        for (int k = 0; k <= PP; k++)
            e[k] = erff(((float)k - 0.5f - up) * ia);

        if (ax == 0) {
            s_px[sid] = pu;
#pragma unroll
            for (int k = 0; k < PP; k++)
                s_lx[sid * PP + k] = 500.0f * (e[k + 1] - e[k]);  // i0*0.5 folded
        } else {
            s_py[sid] = pu;
#pragma unroll
            for (int k = 0; k < PP; k++)
                s_ly[sid * PP + k] = 0.5f * (e[k + 1] - e[k]);
        }
    }
    __syncthreads();

    // 2b) bucket pass: pack (sid, rl, py) into a single int per entry
    if (tid < n) {
        int px = s_px[tid];
        int py = s_py[tid];
        int rl = px - r0;                              // [-5, 31]
        int entry = (tid << 16) | ((rl + 5) << 9) | py;
        int b0 = py >> 5;
        int b1 = (py + PP - 1) >> 5;
        for (int bd = b0; bd <= b1; ++bd) {
            int pos = atomicAdd(&s_bcnt[bd], 1);
            if (pos < BCAP) s_blist[bd][pos] = entry;
        }
    }
    __syncthreads();

    // 3) gather: warp w owns cols [32w, 32w+31]; lane owns 1 col, 32 rows in regs.
    //    One LDS per source for metadata; next entry prefetched.
    int col = (wid << 5) + lane;
    float acc[BH];
#pragma unroll
    for (int r = 0; r < BH; ++r) acc[r] = 0.f;

    int cnt = s_bcnt[wid];
    if (cnt > BCAP) cnt = BCAP;

    int e = (cnt > 0) ? s_blist[wid][0] : 0;
    for (int k = 0; k < cnt; ++k) {
        int e_next = (k + 1 < cnt) ? s_blist[wid][k + 1] : 0;   // prefetch
        int py = e & 511;
        int rl = ((e >> 9) & 63) - 5;                 // warp-uniform
        int sb = (e >> 16) * PP;
        int dc = col - py;
        float ly = ((unsigned)dc < (unsigned)PP) ? s_ly[sb + dc] : 0.f;
        switch (rl) {
#define ACC_CASE(RL) case RL: acc6<RL>(acc, s_lx, sb, ly); break;
            ACC_CASE(-5) ACC_CASE(-4) ACC_CASE(-3) ACC_CASE(-2) ACC_CASE(-1)
            ACC_CASE(0)  ACC_CASE(1)  ACC_CASE(2)  ACC_CASE(3)  ACC_CASE(4)
            ACC_CASE(5)  ACC_CASE(6)  ACC_CASE(7)  ACC_CASE(8)  ACC_CASE(9)
            ACC_CASE(10) ACC_CASE(11) ACC_CASE(12) ACC_CASE(13) ACC_CASE(14)
            ACC_CASE(15) ACC_CASE(16) ACC_CASE(17) ACC_CASE(18) ACC_CASE(19)
            ACC_CASE(20) ACC_CASE(21) ACC_CASE(22) ACC_CASE(23) ACC_CASE(24)
            ACC_CASE(25) ACC_CASE(26) ACC_CASE(27) ACC_CASE(28) ACC_CASE(29)
            ACC_CASE(30) ACC_CASE(31)
#undef ACC_CASE
            default: break;
        }
        e = e_next;
    }

    // 4) store: coalesced (128 B per warp-row), pointer-incremented
    float* p = out + (size_t)b * NXC * NYC + (size_t)r0 * NYC + col;
#pragma unroll
    for (int r = 0; r < BH; ++r) {
        *p = acc[r];
        p += NYC;
    }
}

extern "C" void kernel_launch(void* const* d_in, const int* in_sizes, int n_in,
                              void* d_out, int out_size) {
    const float* z = (const float*)d_in[0];
    float* out = (float*)d_out;
    render_kernel<<<NBANDS, NT>>>(z, out);
}

// round 16
// speedup vs baseline: 1.1025x; 1.1025x over previous
#include <cuda_runtime.h>

#define NXC 512
#define NYC 512
#define PHW 3
#define PP 6                   // patch size
#define BB 128
#define SS 1024
#define BH 32                  // band height (rows)
#define SBH 64                 // super-band: 2 bands per block
#define SB_PER_IMG (NXC / SBH)        // 8
#define NSB (BB * SB_PER_IMG)         // 1024 blocks
#define NT 512                 // threads per block
#define CAP 256                // max sources per super-band (mean ~138)
#define NBKT 16                // 32-col stripes
#define BCAP 32                // per-(band,stripe) capacity (mean ~5.5)

__device__ __forceinline__ float inv_alpha() { return 1.0f / (1.41421356237309515f * 0.92f); }

// Abramowitz-Stegun 7.1.26: |err| <= 1.5e-7, ~11 instr
__device__ __forceinline__ float fast_erf(float x) {
    float ax = fabsf(x);
    float t = __frcp_rn(fmaf(0.3275911f, ax, 1.0f));
    float y = t * fmaf(t, fmaf(t, fmaf(t, fmaf(t, 1.061405429f, -1.453152027f),
                       1.421413741f), -0.284496736f), 0.254829592f);
    float r = 1.0f - y * __expf(-ax * ax);
    return copysignf(r, x);
}

// statically-indexed 6-row accumulate; RL = warp-uniform local patch-origin row
template<int RL>
__device__ __forceinline__ void acc6(float* acc, const float* s_lx, int sb, float ly) {
#pragma unroll
    for (int i = 0; i < PP; ++i) {
        const int r = RL + i;                 // compile-time
        if (r >= 0 && r < BH)
            acc[r] += s_lx[sb + i] * ly;      // static register index
    }
}

__global__ __launch_bounds__(NT, 2) void render_kernel(const float* __restrict__ z,
                                                       float* __restrict__ out) {
    __shared__ float2 s_src[CAP];
    __shared__ float  s_lx[CAP * PP];
    __shared__ float  s_ly[CAP * PP];
    __shared__ int    s_bcnt[2][NBKT];
    __shared__ int    s_blist[2][NBKT][BCAP];  // packed: sid<<16 | (rl+5)<<9 | py
    __shared__ int    s_n;

    int blk = blockIdx.x;
    int b   = blk >> 3;                               // image
    int r0  = (blk & (SB_PER_IMG - 1)) << 6;          // first global row of super-band
    int tid = threadIdx.x;
    int wid = tid >> 5;
    int lane = tid & 31;

    if (tid == 0) s_n = 0;
    if (tid < 2 * NBKT) ((int*)s_bcnt)[tid] = 0;
    __syncthreads();

    // 1) scan this image's sources: float2 loads, 2 sources per thread, 1 iteration
    {
        const float* zx = z + (size_t)b * 2 * SS;
        float2 x01 = ((const float2*)zx)[tid];
        float2 y01 = ((const float2*)(zx + SS))[tid];
#pragma unroll
        for (int j = 0; j < 2; ++j) {
            float x0 = j ? x01.y : x01.x;
            float y0 = j ? y01.y : y01.x;
            int patchx = __float2int_rn(x0) - PHW;
            int patchy = __float2int_rn(y0) - PHW;
            bool valid = (patchx >= 0) & (patchx < NXC - PP) &
                         (patchy >= 0) & (patchy < NYC - PP);
            bool hit = valid & (patchx >= r0 - (PP - 1)) & (patchx < r0 + SBH);
            if (hit) {
                int pos = atomicAdd(&s_n, 1);
                if (pos < CAP) s_src[pos] = make_float2(x0, y0);
            }
        }
    }
    __syncthreads();

    int n = s_n;
    if (n > CAP) n = CAP;

    // 2) setup: 2 threads per source (one per axis); the y-thread also buckets
    //    the source into per-(band, col-stripe) lists.
    if (tid < 2 * n) {
        int sid = tid >> 1;
        int ax  = tid & 1;
        float2 xy = s_src[sid];
        float u0 = ax ? xy.y : xy.x;
        int pu = __float2int_rn(u0) - PHW;
        float up = u0 - (float)pu;
        const float ia = inv_alpha();

        float e[PP + 1];
#pragma unroll
        for (int k = 0; k <= PP; k++)
            e[k] = fast_erf(((float)k - 0.5f - up) * ia);

        if (ax == 0) {
#pragma unroll
            for (int k = 0; k < PP; k++)
                s_lx[sid * PP + k] = 500.0f * (e[k + 1] - e[k]);  // i0*0.5 folded
        } else {
            int py = pu;
#pragma unroll
            for (int k = 0; k < PP; k++)
                s_ly[sid * PP + k] = 0.5f * (e[k + 1] - e[k]);

            int px = __float2int_rn(xy.x) - PHW;
            int rl = px - r0;                          // [-5, 63]
            int st0 = py >> 5;
            int st1 = (py + PP - 1) >> 5;
            if (rl < BH) {                             // touches band 0
                int entry = (sid << 16) | ((rl + 5) << 9) | py;
                for (int st = st0; st <= st1; ++st) {
                    int pos = atomicAdd(&s_bcnt[0][st], 1);
                    if (pos < BCAP) s_blist[0][st][pos] = entry;
                }
            }
            if (rl + PP - 1 >= BH) {                   // touches band 1
                int rl1 = rl - BH;                     // [-5, 31]
                int entry = (sid << 16) | ((rl1 + 5) << 9) | py;
                for (int st = st0; st <= st1; ++st) {
                    int pos = atomicAdd(&s_bcnt[1][st], 1);
                    if (pos < BCAP) s_blist[1][st][pos] = entry;
                }
            }
        }
    }
    __syncthreads();

    // 3) render both bands, barrier-free: warp w owns cols [32w, 32w+31];
    //    lane owns 1 col, 32 rows in registers; rl warp-uniform -> static dispatch.
    int col = (wid << 5) + lane;
#pragma unroll 1
    for (int bd = 0; bd < 2; ++bd) {
        float acc[BH];
#pragma unroll
        for (int r = 0; r < BH; ++r) acc[r] = 0.f;

        int cnt = s_bcnt[bd][wid];
        if (cnt > BCAP) cnt = BCAP;
        for (int k = 0; k < cnt; ++k) {
            int e  = s_blist[bd][wid][k];
            int py = e & 511;
            int rl = ((e >> 9) & 63) - 5;             // warp-uniform
            int sb = (e >> 16) * PP;
            int dc = col - py;
            float ly = ((unsigned)dc < (unsigned)PP) ? s_ly[sb + dc] : 0.f;
            switch (rl) {
#define ACC_CASE(RL) case RL: acc6<RL>(acc, s_lx, sb, ly); break;
                ACC_CASE(-5) ACC_CASE(-4) ACC_CASE(-3) ACC_CASE(-2) ACC_CASE(-1)
                ACC_CASE(0)  ACC_CASE(1)  ACC_CASE(2)  ACC_CASE(3)  ACC_CASE(4)
                ACC_CASE(5)  ACC_CASE(6)  ACC_CASE(7)  ACC_CASE(8)  ACC_CASE(9)
                ACC_CASE(10) ACC_CASE(11) ACC_CASE(12) ACC_CASE(13) ACC_CASE(14)
                ACC_CASE(15) ACC_CASE(16) ACC_CASE(17) ACC_CASE(18) ACC_CASE(19)
                ACC_CASE(20) ACC_CASE(21) ACC_CASE(22) ACC_CASE(23) ACC_CASE(24)
                ACC_CASE(25) ACC_CASE(26) ACC_CASE(27) ACC_CASE(28) ACC_CASE(29)
                ACC_CASE(30) ACC_CASE(31)
#undef ACC_CASE
                default: break;
            }
        }

        // store: coalesced, immediate-offset addressing
        float* base = out + (size_t)b * NXC * NYC + (size_t)(r0 + bd * BH) * NYC + col;
#pragma unroll
        for (int r = 0; r < BH; ++r)
            base[r * NYC] = acc[r];
    }
}

extern "C" void kernel_launch(void* const* d_in, const int* in_sizes, int n_in,
                              void* d_out, int out_size) {
    const float* z = (const float*)d_in[0];
    float* out = (float*)d_out;
    render_kernel<<<NSB, NT>>>(z, out);
}

// round 17
// speedup vs baseline: 1.1762x; 1.0668x over previous
#include <cuda_runtime.h>

#define NXC 512
#define NYC 512
#define PHW 3
#define PP 6                   // patch size
#define BB 128
#define SS 1024
#define BH 32                  // render band height (rows)
#define NBANDS_BLK 4           // bands per block
#define SBH (BH * NBANDS_BLK)  // 128 rows per block
#define SB_PER_IMG (NXC / SBH)        // 4
#define NSB (BB * SB_PER_IMG)         // 512 blocks
#define NT 512                 // threads per block
#define CAP 384                // max sources per super-band (mean ~276)
#define NBKT 16                // 32-col stripes
#define BCAP 24                // per-(band,stripe) capacity (mean ~5.9)

__device__ __forceinline__ float inv_alpha() { return 1.0f / (1.41421356237309515f * 0.92f); }

// Abramowitz-Stegun 7.1.26: |err| <= 1.5e-7
__device__ __forceinline__ float fast_erf(float x) {
    float ax = fabsf(x);
    float t = __frcp_rn(fmaf(0.3275911f, ax, 1.0f));
    float y = t * fmaf(t, fmaf(t, fmaf(t, fmaf(t, 1.061405429f, -1.453152027f),
                       1.421413741f), -0.284496736f), 0.254829592f);
    float r = 1.0f - y * __expf(-ax * ax);
    return copysignf(r, x);
}

// statically-indexed 6-row accumulate; RL = warp-uniform local patch-origin row
template<int RL>
__device__ __forceinline__ void acc6(float* acc, const float* s_lx, int sb, float ly) {
#pragma unroll
    for (int i = 0; i < PP; ++i) {
        const int r = RL + i;                 // compile-time
        if (r >= 0 && r < BH)
            acc[r] += s_lx[sb + i] * ly;      // static register index
    }
}

__global__ __launch_bounds__(NT, 2) void render_kernel(const float* __restrict__ z,
                                                       float* __restrict__ out) {
    __shared__ float2 s_src[CAP];
    __shared__ float  s_lx[CAP * PP];
    __shared__ float  s_ly[CAP * PP];
    __shared__ int    s_bcnt[NBANDS_BLK][NBKT];
    __shared__ int    s_blist[NBANDS_BLK][NBKT][BCAP];  // sid<<16 | (rlb+5)<<9 | py
    __shared__ int    s_n;

    int blk = blockIdx.x;
    int b   = blk >> 2;                               // image
    int r0  = (blk & (SB_PER_IMG - 1)) << 7;          // first global row of super-band
    int tid = threadIdx.x;
    int wid = tid >> 5;
    int lane = tid & 31;

    if (tid == 0) s_n = 0;
    if (tid < NBANDS_BLK * NBKT) ((int*)s_bcnt)[tid] = 0;
    __syncthreads();

    // 1) scan this image's sources: float2 loads, 2 sources per thread
    {
        const float* zx = z + (size_t)b * 2 * SS;
        float2 x01 = ((const float2*)zx)[tid];
        float2 y01 = ((const float2*)(zx + SS))[tid];
#pragma unroll
        for (int j = 0; j < 2; ++j) {
            float x0 = j ? x01.y : x01.x;
            float y0 = j ? y01.y : y01.x;
            int patchx = __float2int_rn(x0) - PHW;
            int patchy = __float2int_rn(y0) - PHW;
            bool valid = (patchx >= 0) & (patchx < NXC - PP) &
                         (patchy >= 0) & (patchy < NYC - PP);
            bool hit = valid & (patchx >= r0 - (PP - 1)) & (patchx < r0 + SBH);
            if (hit) {
                int pos = atomicAdd(&s_n, 1);
                if (pos < CAP) s_src[pos] = make_float2(x0, y0);
            }
        }
    }
    __syncthreads();

    int n = s_n;
    if (n > CAP) n = CAP;

    // 2) setup: 2 threads per source (one per axis), strided since 2n may exceed NT.
    //    The y-thread also buckets the source into per-(band, col-stripe) lists.
    for (int t = tid; t < 2 * n; t += NT) {
        int sid = t >> 1;
        int ax  = t & 1;
        float2 xy = s_src[sid];
        float u0 = ax ? xy.y : xy.x;
        int pu = __float2int_rn(u0) - PHW;
        float up = u0 - (float)pu;
        const float ia = inv_alpha();

        float e[PP + 1];
#pragma unroll
        for (int k = 0; k <= PP; k++)
            e[k] = fast_erf(((float)k - 0.5f - up) * ia);

        if (ax == 0) {
#pragma unroll
            for (int k = 0; k < PP; k++)
                s_lx[sid * PP + k] = 500.0f * (e[k + 1] - e[k]);  // i0*0.5 folded
        } else {
            int py = pu;
#pragma unroll
            for (int k = 0; k < PP; k++)
                s_ly[sid * PP + k] = 0.5f * (e[k + 1] - e[k]);

            int px = __float2int_rn(xy.x) - PHW;
            int rsb = px - r0;                         // [-5, 127]
            int st0 = py >> 5;
            int st1 = (py + PP - 1) >> 5;
            int bd0 = (rsb < 0) ? 0 : (rsb >> 5);
            int bd1 = (rsb + PP - 1) >> 5;
            if (bd1 >= NBANDS_BLK) bd1 = NBANDS_BLK - 1;
            for (int bd = bd0; bd <= bd1; ++bd) {
                int rlb = rsb - (bd << 5);             // [-5, 31]
                int entry = (sid << 16) | ((rlb + 5) << 9) | py;
                for (int st = st0; st <= st1; ++st) {
                    int pos = atomicAdd(&s_bcnt[bd][st], 1);
                    if (pos < BCAP) s_blist[bd][st][pos] = entry;
                }
            }
        }
    }
    __syncthreads();

    // 3) render 4 bands, barrier-free: warp w owns cols [32w, 32w+31];
    //    lane owns 1 col, 32 rows in registers; rlb warp-uniform -> static dispatch.
    int col = (wid << 5) + lane;
#pragma unroll 1
    for (int bd = 0; bd < NBANDS_BLK; ++bd) {
        float acc[BH];
#pragma unroll
        for (int r = 0; r < BH; ++r) acc[r] = 0.f;

        int cnt = s_bcnt[bd][wid];
        if (cnt > BCAP) cnt = BCAP;
        for (int k = 0; k < cnt; ++k) {
            int e  = s_blist[bd][wid][k];
            int py = e & 511;
            int rl = ((e >> 9) & 63) - 5;             // warp-uniform
            int sb = (e >> 16) * PP;
            int dc = col - py;
            float ly = ((unsigned)dc < (unsigned)PP) ? s_ly[sb + dc] : 0.f;
            switch (rl) {
#define ACC_CASE(RL) case RL: acc6<RL>(acc, s_lx, sb, ly); break;
                ACC_CASE(-5) ACC_CASE(-4) ACC_CASE(-3) ACC_CASE(-2) ACC_CASE(-1)
                ACC_CASE(0)  ACC_CASE(1)  ACC_CASE(2)  ACC_CASE(3)  ACC_CASE(4)
                ACC_CASE(5)  ACC_CASE(6)  ACC_CASE(7)  ACC_CASE(8)  ACC_CASE(9)
                ACC_CASE(10) ACC_CASE(11) ACC_CASE(12) ACC_CASE(13) ACC_CASE(14)
                ACC_CASE(15) ACC_CASE(16) ACC_CASE(17) ACC_CASE(18) ACC_CASE(19)
                ACC_CASE(20) ACC_CASE(21) ACC_CASE(22) ACC_CASE(23) ACC_CASE(24)
                ACC_CASE(25) ACC_CASE(26) ACC_CASE(27) ACC_CASE(28) ACC_CASE(29)
                ACC_CASE(30) ACC_CASE(31)
#undef ACC_CASE
                default: break;
            }
        }

        // store: coalesced, immediate-offset addressing
        float* base = out + (size_t)b * NXC * NYC + (size_t)(r0 + bd * BH) * NYC + col;
#pragma unroll
        for (int r = 0; r < BH; ++r)
            base[r * NYC] = acc[r];
    }
}

extern "C" void kernel_launch(void* const* d_in, const int* in_sizes, int n_in,
                              void* d_out, int out_size) {
    const float* z = (const float*)d_in[0];
    float* out = (float*)d_out;
    render_kernel<<<NSB, NT>>>(z, out);
}